// round 2
// baseline (speedup 1.0000x reference)
#include <cuda_runtime.h>

#define BB   256
#define TT   2048
#define QD   1024
#define AD   128
#define DCH  8
#define DKK  21
#define PLL  11
#define MROW 24   // 21 taps + v + T_b + pad

// Per-batch fused conv weights: M_b[a][0..20], v[a] at [21], T_b[a] at [22]
__device__ float g_M[BB * AD * MROW];

__device__ __forceinline__ float tanh_fast(float x) {
    float y;
    asm("tanh.approx.f32 %0, %1;" : "=f"(y) : "f"(x));
    return y;
}

// ---------------------------------------------------------------------------
// Prep: h = tanh(q@W^T + Wb); G_b = h@V^T; M_b = U@F + T@G_b  (one block/batch)
// ---------------------------------------------------------------------------
__global__ __launch_bounds__(128) void dca_prep_kernel(
    const float* __restrict__ query, const float* __restrict__ W_w,
    const float* __restrict__ W_b,   const float* __restrict__ V_w,
    const float* __restrict__ F_w,   const float* __restrict__ U_w,
    const float* __restrict__ T_w,   const float* __restrict__ T_b,
    const float* __restrict__ v_w)
{
    __shared__ float shq[QD];
    __shared__ float shh[AD];
    __shared__ float shG[DCH * DKK];
    const int b = blockIdx.x, tid = threadIdx.x;

    for (int j = tid; j < QD; j += 128) shq[j] = query[b * QD + j];
    __syncthreads();

    {   // h[a] = tanh(dot(q, W_w[a,:]) + W_b[a])
        const int a = tid;
        const float4* wr = (const float4*)(W_w + a * QD);
        const float4* qr = (const float4*)shq;
        float a0 = 0.f, a1 = 0.f, a2 = 0.f, a3 = 0.f;
#pragma unroll 8
        for (int j = 0; j < QD / 4; j++) {
            float4 wv = wr[j], qv = qr[j];
            a0 += wv.x * qv.x; a1 += wv.y * qv.y;
            a2 += wv.z * qv.z; a3 += wv.w * qv.w;
        }
        shh[a] = tanhf(a0 + a1 + a2 + a3 + W_b[a]);
    }
    __syncthreads();

    // G_b[i] = dot(h, V_w[i,:]), i in [0,168)
    for (int i = tid; i < DCH * DKK; i += 128) {
        const float4* vr = (const float4*)(V_w + i * AD);
        const float4* hr = (const float4*)shh;
        float acc = 0.f;
#pragma unroll
        for (int j = 0; j < AD / 4; j++) {
            float4 vv = vr[j], hv = hr[j];
            acc += vv.x * hv.x + vv.y * hv.y + vv.z * hv.z + vv.w * hv.w;
        }
        shG[i] = acc;
    }
    __syncthreads();

    // M_b[a,k] = sum_c U[a,c]*F[c,k] + T[a,c]*G_b[c,k]
    float* Mb = g_M + b * AD * MROW;
    for (int idx = tid; idx < AD * DKK; idx += 128) {
        const int a = idx / DKK, k = idx - a * DKK;
        float m = 0.f;
#pragma unroll
        for (int c = 0; c < DCH; c++)
            m += U_w[a * DCH + c] * F_w[c * DKK + k]
               + T_w[a * DCH + c] * shG[c * DKK + k];
        Mb[a * MROW + k] = m;
    }
    if (tid < AD) {
        Mb[tid * MROW + 21] = v_w[tid];
        Mb[tid * MROW + 22] = T_b[tid];
        Mb[tid * MROW + 23] = 0.f;
    }
}

// ---------------------------------------------------------------------------
// Main: per block = one batch row. Each thread computes 4 consecutive t.
//   z_j[a] = T_b[a] + sum_k M_b[a,k] * w[t0+j-10+k]
//   e_j    = sum_a v[a]*tanh(z_j[a]) + log(clip(prior_j, 1e-6))
// then in-block softmax over T.
// ---------------------------------------------------------------------------
#define TAP(mc, k) { z0 += (mc) * w[(k)];     z1 += (mc) * w[(k) + 1]; \
                     z2 += (mc) * w[(k) + 2]; z3 += (mc) * w[(k) + 3]; }

__global__ __launch_bounds__(512, 2) void dca_main_kernel(
    const float* __restrict__ alignment, const float* __restrict__ P,
    float* __restrict__ out)
{
    __shared__ float sal[TT + 20];
    __shared__ float sw[AD * MROW];
    __shared__ float se[TT];
    __shared__ float sp[PLL];
    __shared__ float red[16];

    const int b = blockIdx.x, tid = threadIdx.x;

    for (int i = tid; i < TT; i += 512) sal[10 + i] = alignment[b * TT + i];
    if (tid < 10) { sal[tid] = 0.f; sal[TT + 10 + tid] = 0.f; }
    for (int i = tid; i < AD * MROW; i += 512) sw[i] = g_M[b * AD * MROW + i];
    if (tid < PLL) sp[tid] = P[tid];
    __syncthreads();

    const int t0 = tid * 4;
    float w[24];
#pragma unroll
    for (int k = 0; k < 24; k++) w[k] = sal[t0 + k];

    float e0 = 0.f, e1 = 0.f, e2 = 0.f, e3 = 0.f;

#pragma unroll 1
    for (int a = 0; a < AD; a++) {
        const float4* wp = (const float4*)(sw + a * MROW);
        float z0 = 0.f, z1 = 0.f, z2 = 0.f, z3 = 0.f;
        float4 m;
        m = wp[0]; TAP(m.x, 0)  TAP(m.y, 1)  TAP(m.z, 2)  TAP(m.w, 3)
        m = wp[1]; TAP(m.x, 4)  TAP(m.y, 5)  TAP(m.z, 6)  TAP(m.w, 7)
        m = wp[2]; TAP(m.x, 8)  TAP(m.y, 9)  TAP(m.z, 10) TAP(m.w, 11)
        m = wp[3]; TAP(m.x, 12) TAP(m.y, 13) TAP(m.z, 14) TAP(m.w, 15)
        m = wp[4]; TAP(m.x, 16) TAP(m.y, 17) TAP(m.z, 18) TAP(m.w, 19)
        m = wp[5]; TAP(m.x, 20)
        const float v = m.y, tb = m.z;
        e0 += v * tanh_fast(z0 + tb);
        e1 += v * tanh_fast(z1 + tb);
        e2 += v * tanh_fast(z2 + tb);
        e3 += v * tanh_fast(z3 + tb);
    }

    // prior: p_j = log(clip(sum_{k<11} w[j+k]*P[k], 1e-6))
    {
        float s0 = 0.f, s1 = 0.f, s2 = 0.f, s3 = 0.f;
#pragma unroll
        for (int k = 0; k < PLL; k++) {
            const float pk = sp[k];
            s0 += pk * w[k];     s1 += pk * w[k + 1];
            s2 += pk * w[k + 2]; s3 += pk * w[k + 3];
        }
        e0 += __logf(fmaxf(s0, 1e-6f));
        e1 += __logf(fmaxf(s1, 1e-6f));
        e2 += __logf(fmaxf(s2, 1e-6f));
        e3 += __logf(fmaxf(s3, 1e-6f));
    }

    se[t0] = e0; se[t0 + 1] = e1; se[t0 + 2] = e2; se[t0 + 3] = e3;

    const int lane = tid & 31, wid = tid >> 5;

    // block max
    float mx = fmaxf(fmaxf(e0, e1), fmaxf(e2, e3));
#pragma unroll
    for (int o = 16; o; o >>= 1) mx = fmaxf(mx, __shfl_xor_sync(~0u, mx, o));
    if (lane == 0) red[wid] = mx;
    __syncthreads();
    mx = red[0];
#pragma unroll
    for (int i = 1; i < 16; i++) mx = fmaxf(mx, red[i]);
    __syncthreads();

    // exp + block sum
    const float x0 = __expf(e0 - mx), x1 = __expf(e1 - mx);
    const float x2 = __expf(e2 - mx), x3 = __expf(e3 - mx);
    float sm = (x0 + x1) + (x2 + x3);
#pragma unroll
    for (int o = 16; o; o >>= 1) sm += __shfl_xor_sync(~0u, sm, o);
    if (lane == 0) red[wid] = sm;
    __syncthreads();
    sm = red[0];
#pragma unroll
    for (int i = 1; i < 16; i++) sm += red[i];

    const float inv = 1.0f / sm;
    float* o4 = out + b * TT + t0;
    o4[0] = x0 * inv; o4[1] = x1 * inv; o4[2] = x2 * inv; o4[3] = x3 * inv;
}

extern "C" void kernel_launch(void* const* d_in, const int* in_sizes, int n_in,
                              void* d_out, int out_size)
{
    const float* query     = (const float*)d_in[0];
    const float* alignment = (const float*)d_in[1];
    const float* P         = (const float*)d_in[2];
    const float* W_w       = (const float*)d_in[3];
    const float* W_b       = (const float*)d_in[4];
    const float* V_w       = (const float*)d_in[5];
    const float* F_w       = (const float*)d_in[6];
    const float* U_w       = (const float*)d_in[7];
    const float* T_w       = (const float*)d_in[8];
    const float* T_b       = (const float*)d_in[9];
    const float* v_w       = (const float*)d_in[10];
    float* out = (float*)d_out;

    dca_prep_kernel<<<BB, 128>>>(query, W_w, W_b, V_w, F_w, U_w, T_w, T_b, v_w);
    dca_main_kernel<<<BB, 512>>>(alignment, P, out);
}